// round 3
// baseline (speedup 1.0000x reference)
#include <cuda_runtime.h>
#include <math.h>

// ---- problem constants ----
#define Bsz 4096
#define Lm  30
#define Wm  5
#define Am  30
#define Em  128
#define Cch 40
#define Hm  128
#define Tm  3
#define LIN 200
#define FK  208          // padded K for GEMM
#define Nt  (Bsz*Lm)     // 122880 tokens
#define G4  512          // 4*H gates

typedef unsigned long long u64;

// ---- packed f32x2 helpers (FFMA2 path, sm_103a) ----
__device__ __forceinline__ u64 pack2(float lo, float hi) {
    u64 r; asm("mov.b64 %0,{%1,%2};" : "=l"(r) : "f"(lo), "f"(hi)); return r;
}
__device__ __forceinline__ u64 splat2(float v) { return pack2(v, v); }
__device__ __forceinline__ u64 fma2(u64 a, u64 b, u64 c) {
    u64 d; asm("fma.rn.f32x2 %0,%1,%2,%3;" : "=l"(d) : "l"(a), "l"(b), "l"(c)); return d;
}
__device__ __forceinline__ void unpack2(u64 v, float& lo, float& hi) {
    asm("mov.b64 {%0,%1},%2;" : "=f"(lo), "=f"(hi) : "l"(v));
}
__device__ __forceinline__ float sigf(float x) {
    return __fdividef(1.f, 1.f + __expf(-x));
}
__device__ __forceinline__ float tanhfast(float x) {
    return __fdividef(2.f, 1.f + __expf(-2.f * x)) - 1.f;
}

// ---- device scratch (static, allowed) ----
__device__ float g_M[Am*Cch*3];        // folded emb*conv*bn
__device__ float g_bias1[Cch];
__device__ float g_wihP[2][G4*FK];     // padded input weights [dir][g][k]
__device__ float g_whhT[2][Hm*G4];     // transposed recurrent weights [dir][k][g]
__device__ float g_fcf[Tm*Hm];
__device__ float g_fcb[Tm*Hm];
__device__ float g_cbias[Tm];
__device__ float g_feat[(size_t)Nt*FK];        // ~102 MB
__device__ float g_gates[2][(size_t)Nt*G4];    // ~503 MB
__device__ float g_h[2][(size_t)Nt*Hm];        // ~126 MB
__device__ float g_emis[(size_t)Nt*Tm];

// ======================= prep kernels =======================
__global__ void prep_tables(const float* __restrict__ emb,
                            const float* __restrict__ conv_w,
                            const float* __restrict__ conv_b,
                            const float* __restrict__ g1,
                            const float* __restrict__ b1,
                            const float* __restrict__ m1,
                            const float* __restrict__ v1)
{
    int i = blockIdx.x*blockDim.x + threadIdx.x;
    if (i < Am*Cch*3) {
        int k = i % 3;
        int c = (i/3) % Cch;
        int a = i / (3*Cch);
        float s = 0.f;
        for (int e = 0; e < Em; e++)
            s += emb[a*Em + e] * conv_w[(c*Em + e)*3 + k];
        float sc = g1[c] * rsqrtf(v1[c] + 1e-5f);
        g_M[i] = s * sc;
    } else if (i < Am*Cch*3 + Cch) {
        int c = i - Am*Cch*3;
        float sc = g1[c] * rsqrtf(v1[c] + 1e-5f);
        g_bias1[c] = (conv_b[c] - m1[c]) * sc + b1[c];
    }
}

__global__ void prep_pack(const float* __restrict__ wihf, const float* __restrict__ whhf,
                          const float* __restrict__ wihb, const float* __restrict__ whhb)
{
    int stride = gridDim.x * blockDim.x;
    int t0 = blockIdx.x*blockDim.x + threadIdx.x;
    for (int i = t0; i < G4*FK; i += stride) {
        int g = i / FK, k = i % FK;
        float vf = (k < LIN) ? wihf[g*LIN + k] : 0.f;
        float vb = (k < LIN) ? wihb[g*LIN + k] : 0.f;
        g_wihP[0][i] = vf;
        g_wihP[1][i] = vb;
    }
    for (int i = t0; i < Hm*G4; i += stride) {
        int k = i / G4, g = i % G4;
        g_whhT[0][i] = whhf[g*Hm + k];
        g_whhT[1][i] = whhb[g*Hm + k];
    }
}

__global__ void prep_fc(const float* __restrict__ g2, const float* __restrict__ b2,
                        const float* __restrict__ m2, const float* __restrict__ v2,
                        const float* __restrict__ fcw, const float* __restrict__ fcbias)
{
    int t = threadIdx.x;
    if (t < Hm) {
        float s2a = g2[t]       * rsqrtf(v2[t]       + 1e-5f);
        float s2b = g2[Hm + t]  * rsqrtf(v2[Hm + t]  + 1e-5f);
        for (int tt = 0; tt < Tm; tt++) {
            g_fcf[tt*Hm + t] = fcw[tt*2*Hm + t]      * s2a;
            g_fcb[tt*Hm + t] = fcw[tt*2*Hm + Hm + t] * s2b;
        }
    }
    if (t < Tm) {
        float s = fcbias[t];
        for (int j = 0; j < 2*Hm; j++) {
            float s2 = g2[j] * rsqrtf(v2[j] + 1e-5f);
            s += (b2[j] - m2[j]*s2) * fcw[t*2*Hm + j];
        }
        g_cbias[t] = s;
    }
}

// ======================= featurize (conv+bn+relu+pool) =======================
__global__ void featurize(const int* __restrict__ x)
{
    int idx = blockIdx.x*blockDim.x + threadIdx.x;
    if (idx >= Nt*Cch) return;
    int n = idx / Cch, c = idx % Cch;
    int sym[Wm];
#pragma unroll
    for (int w = 0; w < Wm; w++) sym[w] = x[n*Wm + w];
    float y[Wm];
    float bb = g_bias1[c];
#pragma unroll
    for (int w = 0; w < Wm; w++) {
        float v = bb;
#pragma unroll
        for (int k = 0; k < 3; k++) {
            int p = w + k - 1;
            if (p >= 0 && p < Wm)
                v += g_M[sym[p]*(Cch*3) + c*3 + k];
        }
        y[w] = fmaxf(v, 0.f);
    }
    size_t base = (size_t)n*FK + c*Wm;
#pragma unroll
    for (int w = 0; w < Wm; w++) {
        float p = y[w];
        if (w > 0)      p = fmaxf(p, y[w-1]);
        if (w < Wm-1)   p = fmaxf(p, y[w+1]);
        g_feat[base + w] = p;
    }
    if (c < FK - LIN) g_feat[(size_t)n*FK + LIN + c] = 0.f; // zero pad columns
}

// ======================= input GEMM v3 (f32x2, 128x128, double-buffered) =======================
// block tile 128(M) x 128(N), 256 threads, per-thread 8(M as 4 f32x2 pairs) x 8(N).
// B stored pre-splatted as (b,b) u64 pairs -> no MOV splats in inner loop.
// blockIdx.x = dir*4 + n_tile so all consumers of an A-panel run adjacently.
#define NCH 13   // 208/16 k-chunks
__global__ __launch_bounds__(256, 2) void gemm_gates3(const float* __restrict__ bias_f,
                                                      const float* __restrict__ bias_b)
{
    int dir = blockIdx.x >> 2;
    int n0  = (blockIdx.x & 3) * 128;
    int m0  = blockIdx.y * 128;
    const float* __restrict__ A  = g_feat;
    const float* __restrict__ Bt = g_wihP[dir];
    float* __restrict__ Co = g_gates[dir];
    const float* __restrict__ bias = dir ? bias_b : bias_f;

    __shared__ __align__(16) float Asf[2][16][130];   // [buf][k][row]
    __shared__ __align__(16) u64   Bsp[2][16][8][17]; // [buf][k][i][tn] pre-splatted

    int t  = threadIdx.x;
    int tm = t >> 4;          // 0..15 -> 8 M rows (4 pairs)
    int tn = t & 15;          // 0..15 -> 8 N cols
    int lr = t >> 1;          // 0..127 load row
    int lc = (t & 1) * 8;     // 0 or 8 load k offset

    const float* aLd = A  + (size_t)(m0 + lr)*FK + lc;
    const float* bLd = Bt + (size_t)(n0 + lr)*FK + lc;
    int bi = lr & 7, bslot = lr >> 3;

    u64 acc2[4][8];
#pragma unroll
    for (int q = 0; q < 4; q++)
#pragma unroll
        for (int i = 0; i < 8; i++) acc2[q][i] = 0ULL;

    // prologue: load + store chunk 0
    float4 a0 = *(const float4*)(aLd);
    float4 a1 = *(const float4*)(aLd + 4);
    float4 b0 = *(const float4*)(bLd);
    float4 b1 = *(const float4*)(bLd + 4);
    {
        float av[8] = {a0.x,a0.y,a0.z,a0.w,a1.x,a1.y,a1.z,a1.w};
        float bv[8] = {b0.x,b0.y,b0.z,b0.w,b1.x,b1.y,b1.z,b1.w};
#pragma unroll
        for (int ii = 0; ii < 8; ii++) {
            Asf[0][lc+ii][lr] = av[ii];
            Bsp[0][lc+ii][bi][bslot] = splat2(bv[ii]);
        }
    }
    __syncthreads();

    int cur = 0;
    for (int c = 0; c < NCH; c++) {
        if (c + 1 < NCH) {
            const float* ap = aLd + (c+1)*16;
            const float* bp = bLd + (c+1)*16;
            a0 = *(const float4*)(ap);
            a1 = *(const float4*)(ap + 4);
            b0 = *(const float4*)(bp);
            b1 = *(const float4*)(bp + 4);
        }
#pragma unroll
        for (int kk = 0; kk < 16; kk++) {
            const u64* ap64 = (const u64*)&Asf[cur][kk][tm*8];
            u64 am0 = ap64[0], am1 = ap64[1], am2 = ap64[2], am3 = ap64[3];
            u64 bs[8];
#pragma unroll
            for (int i = 0; i < 8; i++) bs[i] = Bsp[cur][kk][i][tn];
#pragma unroll
            for (int i = 0; i < 8; i++) {
                acc2[0][i] = fma2(am0, bs[i], acc2[0][i]);
                acc2[1][i] = fma2(am1, bs[i], acc2[1][i]);
                acc2[2][i] = fma2(am2, bs[i], acc2[2][i]);
                acc2[3][i] = fma2(am3, bs[i], acc2[3][i]);
            }
        }
        __syncthreads();
        if (c + 1 < NCH) {
            int nxt = cur ^ 1;
            float av[8] = {a0.x,a0.y,a0.z,a0.w,a1.x,a1.y,a1.z,a1.w};
            float bv[8] = {b0.x,b0.y,b0.z,b0.w,b1.x,b1.y,b1.z,b1.w};
#pragma unroll
            for (int ii = 0; ii < 8; ii++) {
                Asf[nxt][lc+ii][lr] = av[ii];
                Bsp[nxt][lc+ii][bi][bslot] = splat2(bv[ii]);
            }
            __syncthreads();
            cur = nxt;
        }
    }

    int gcol = n0 + tn*8;
    float bb[8];
#pragma unroll
    for (int i = 0; i < 8; i++) bb[i] = bias[gcol + i];
#pragma unroll
    for (int q = 0; q < 4; q++) {
        float lo[8], hi[8];
#pragma unroll
        for (int i = 0; i < 8; i++) unpack2(acc2[q][i], lo[i], hi[i]);
        size_t r = (size_t)(m0 + tm*8 + 2*q);
        float4 o;
        o.x = lo[0]+bb[0]; o.y = lo[1]+bb[1]; o.z = lo[2]+bb[2]; o.w = lo[3]+bb[3];
        *(float4*)(Co + r*G4 + gcol) = o;
        o.x = lo[4]+bb[4]; o.y = lo[5]+bb[5]; o.z = lo[6]+bb[6]; o.w = lo[7]+bb[7];
        *(float4*)(Co + r*G4 + gcol + 4) = o;
        o.x = hi[0]+bb[0]; o.y = hi[1]+bb[1]; o.z = hi[2]+bb[2]; o.w = hi[3]+bb[3];
        *(float4*)(Co + (r+1)*G4 + gcol) = o;
        o.x = hi[4]+bb[4]; o.y = hi[5]+bb[5]; o.z = hi[6]+bb[6]; o.w = hi[7]+bb[7];
        *(float4*)(Co + (r+1)*G4 + gcol + 4) = o;
    }
}

// ======================= LSTM recurrence (both dirs fused, f32x2) =======================
__global__ __launch_bounds__(256, 2) void lstm_fused()
{
    int dir = blockIdx.x >> 7;
    int blk = blockIdx.x & 127;
    const float* __restrict__ gates = g_gates[dir];
    const float* __restrict__ whhT  = g_whhT[dir];
    float* __restrict__ hout        = g_h[dir];

    __shared__ __align__(16) float hs[2][Hm][36];

    int t = threadIdx.x;
    int j = t & 127;
    int half = t >> 7;
    int r0 = blk * 32 + half * 16;

    for (int i = t; i < 2*Hm*36; i += 256) ((float*)hs)[i] = 0.f;

    float cst[16];
#pragma unroll
    for (int r = 0; r < 16; r++) cst[r] = 0.f;
    __syncthreads();

    int cur = 0;
    const float* wp = whhT + j;

    for (int li = 0; li < Lm; li++) {
        int l = dir ? (Lm-1-li) : li;

        u64 acc2[4][8];
#pragma unroll
        for (int g = 0; g < 4; g++)
#pragma unroll
            for (int q = 0; q < 8; q++) {
                size_t base = ((size_t)(r0 + 2*q)*Lm + l)*G4 + g*128 + j;
                float lo = gates[base];
                float hi = gates[base + (size_t)Lm*G4];
                acc2[g][q] = pack2(lo, hi);
            }

#pragma unroll 4
        for (int k = 0; k < Hm; k++) {
            float w0 = wp[k*G4 + 0];
            float w1 = wp[k*G4 + 128];
            float w2 = wp[k*G4 + 256];
            float w3 = wp[k*G4 + 384];
            u64 w0p = splat2(w0), w1p = splat2(w1);
            u64 w2p = splat2(w2), w3p = splat2(w3);
            const ulonglong2* hp = (const ulonglong2*)&hs[cur][k][half*16];
#pragma unroll
            for (int qq = 0; qq < 4; qq++) {
                ulonglong2 hv2 = hp[qq];
                acc2[0][2*qq]   = fma2(w0p, hv2.x, acc2[0][2*qq]);
                acc2[1][2*qq]   = fma2(w1p, hv2.x, acc2[1][2*qq]);
                acc2[2][2*qq]   = fma2(w2p, hv2.x, acc2[2][2*qq]);
                acc2[3][2*qq]   = fma2(w3p, hv2.x, acc2[3][2*qq]);
                acc2[0][2*qq+1] = fma2(w0p, hv2.y, acc2[0][2*qq+1]);
                acc2[1][2*qq+1] = fma2(w1p, hv2.y, acc2[1][2*qq+1]);
                acc2[2][2*qq+1] = fma2(w2p, hv2.y, acc2[2][2*qq+1]);
                acc2[3][2*qq+1] = fma2(w3p, hv2.y, acc2[3][2*qq+1]);
            }
        }

#pragma unroll
        for (int q = 0; q < 8; q++) {
            float zi0,zi1,zf0,zf1,zg0,zg1,zo0,zo1;
            unpack2(acc2[0][q], zi0, zi1);
            unpack2(acc2[1][q], zf0, zf1);
            unpack2(acc2[2][q], zg0, zg1);
            unpack2(acc2[3][q], zo0, zo1);
            {
                float ig = sigf(zi0), fg = sigf(zf0);
                float gg = tanhfast(zg0), og = sigf(zo0);
                float cn = fg*cst[2*q] + ig*gg;
                cst[2*q] = cn;
                float hn = og * tanhfast(cn);
                hs[cur^1][j][half*16 + 2*q] = hn;
                hout[((size_t)(r0 + 2*q)*Lm + l)*Hm + j] = hn;
            }
            {
                float ig = sigf(zi1), fg = sigf(zf1);
                float gg = tanhfast(zg1), og = sigf(zo1);
                float cn = fg*cst[2*q+1] + ig*gg;
                cst[2*q+1] = cn;
                float hn = og * tanhfast(cn);
                hs[cur^1][j][half*16 + 2*q + 1] = hn;
                hout[((size_t)(r0 + 2*q + 1)*Lm + l)*Hm + j] = hn;
            }
        }
        cur ^= 1;
        __syncthreads();
    }
}

// ======================= emission (BN2+FC folded) =======================
__global__ void emission_kernel()
{
    int gt = blockIdx.x*blockDim.x + threadIdx.x;
    int warp = gt >> 5;
    int lane = threadIdx.x & 31;
    if (warp >= Nt) return;
    float4 hf4 = *(const float4*)&g_h[0][(size_t)warp*Hm + lane*4];
    float4 hb4 = *(const float4*)&g_h[1][(size_t)warp*Hm + lane*4];
#pragma unroll
    for (int tt = 0; tt < Tm; tt++) {
        float4 f4 = *(const float4*)&g_fcf[tt*Hm + lane*4];
        float4 b4 = *(const float4*)&g_fcb[tt*Hm + lane*4];
        float s = hf4.x*f4.x + hf4.y*f4.y + hf4.z*f4.z + hf4.w*f4.w
                + hb4.x*b4.x + hb4.y*b4.y + hb4.z*b4.z + hb4.w*b4.w;
#pragma unroll
        for (int o = 16; o; o >>= 1) s += __shfl_xor_sync(0xffffffffu, s, o);
        if (lane == 0) g_emis[(size_t)warp*Tm + tt] = s + g_cbias[tt];
    }
}

// ======================= Viterbi =======================
__global__ void viterbi_kernel(const int* __restrict__ x,
                               const float* __restrict__ trans,
                               const float* __restrict__ start_t,
                               const float* __restrict__ end_t,
                               float* __restrict__ out)
{
    int b = blockIdx.x*blockDim.x + threadIdx.x;
    if (b >= Bsz) return;
    float tr[9];
#pragma unroll
    for (int i = 0; i < 9; i++) tr[i] = trans[i];
    const float* em = g_emis + (size_t)b*Lm*Tm;
    float sc[3];
#pragma unroll
    for (int t = 0; t < 3; t++) sc[t] = start_t[t] + em[t];

    unsigned char hist[Lm-1][3];
    for (int l = 1; l < Lm; l++) {
        bool m = x[(b*Lm + l)*Wm + 2] > 0;
        float ns[3];
#pragma unroll
        for (int t = 0; t < 3; t++) {
            float best = sc[0] + tr[0*3 + t];
            int bp = 0;
#pragma unroll
            for (int p = 1; p < 3; p++) {
                float v = sc[p] + tr[p*3 + t];
                if (v > best) { best = v; bp = p; }
            }
            hist[l-1][t] = (unsigned char)bp;
            ns[t] = best + em[l*Tm + t];
        }
        if (m) { sc[0]=ns[0]; sc[1]=ns[1]; sc[2]=ns[2]; }
    }
#pragma unroll
    for (int t = 0; t < 3; t++) sc[t] += end_t[t];
    float best = sc[0]; int last = 0;
    if (sc[1] > best) { best = sc[1]; last = 1; }
    if (sc[2] > best) { best = sc[2]; last = 2; }
    out[b] = best;

    float* tagout = out + Bsz;
    int tag = last;
    tagout[(size_t)b*Lm + (Lm-1)] = (float)tag;
    for (int i = Lm-2; i >= 0; i--) {
        int prev = hist[i][tag];
        bool m = x[(b*Lm + i + 1)*Wm + 2] > 0;
        if (m) tag = prev;
        tagout[(size_t)b*Lm + i] = (float)tag;
    }
}

// ======================= launch =======================
extern "C" void kernel_launch(void* const* d_in, const int* in_sizes, int n_in,
                              void* d_out, int out_size)
{
    (void)in_sizes; (void)n_in; (void)out_size;
    const int*   x      = (const int*)  d_in[0];
    const float* emb    = (const float*)d_in[1];
    const float* conv_w = (const float*)d_in[2];
    const float* conv_b = (const float*)d_in[3];
    const float* bn1_g  = (const float*)d_in[4];
    const float* bn1_b  = (const float*)d_in[5];
    const float* bn1_m  = (const float*)d_in[6];
    const float* bn1_v  = (const float*)d_in[7];
    const float* w_ih_f = (const float*)d_in[8];
    const float* w_hh_f = (const float*)d_in[9];
    const float* b_f    = (const float*)d_in[10];
    const float* w_ih_b = (const float*)d_in[11];
    const float* w_hh_b = (const float*)d_in[12];
    const float* b_b    = (const float*)d_in[13];
    const float* bn2_g  = (const float*)d_in[14];
    const float* bn2_b  = (const float*)d_in[15];
    const float* bn2_m  = (const float*)d_in[16];
    const float* bn2_v  = (const float*)d_in[17];
    const float* fc_w   = (const float*)d_in[18];
    const float* fc_b   = (const float*)d_in[19];
    const float* trans  = (const float*)d_in[20];
    const float* start_t= (const float*)d_in[21];
    const float* end_t  = (const float*)d_in[22];
    float* out = (float*)d_out;

    prep_tables<<<(Am*Cch*3 + Cch + 255)/256, 256>>>(emb, conv_w, conv_b,
                                                     bn1_g, bn1_b, bn1_m, bn1_v);
    prep_pack<<<512, 256>>>(w_ih_f, w_hh_f, w_ih_b, w_hh_b);
    prep_fc<<<1, 256>>>(bn2_g, bn2_b, bn2_m, bn2_v, fc_w, fc_b);

    featurize<<<(Nt*Cch + 255)/256, 256>>>(x);

    dim3 gg(8, Nt/128);
    gemm_gates3<<<gg, 256>>>(b_f, b_b);

    lstm_fused<<<256, 256>>>();

    emission_kernel<<<(Nt + 3)/4, 128>>>();

    viterbi_kernel<<<(Bsz + 127)/128, 128>>>(x, trans, start_t, end_t, out);
}

// round 5
// speedup vs baseline: 1.0780x; 1.0780x over previous
#include <cuda_runtime.h>
#include <math.h>

// ---- problem constants ----
#define Bsz 4096
#define Lm  30
#define Wm  5
#define Am  30
#define Em  128
#define Cch 40
#define Hm  128
#define Tm  3
#define LIN 200
#define FK  208          // padded K for GEMM
#define Nt  (Bsz*Lm)     // 122880 tokens
#define G4  512          // 4*H gates
#define NCH 13           // 208/16 k-chunks

typedef unsigned long long u64;

// ---- packed f32x2 helpers (FFMA2 path, sm_103a) ----
__device__ __forceinline__ u64 pack2(float lo, float hi) {
    u64 r; asm("mov.b64 %0,{%1,%2};" : "=l"(r) : "f"(lo), "f"(hi)); return r;
}
__device__ __forceinline__ u64 splat2(float v) { return pack2(v, v); }
__device__ __forceinline__ u64 fma2(u64 a, u64 b, u64 c) {
    u64 d; asm("fma.rn.f32x2 %0,%1,%2,%3;" : "=l"(d) : "l"(a), "l"(b), "l"(c)); return d;
}
__device__ __forceinline__ void unpack2(u64 v, float& lo, float& hi) {
    asm("mov.b64 {%0,%1},%2;" : "=f"(lo), "=f"(hi) : "l"(v));
}
__device__ __forceinline__ float sigf(float x) {
    return __fdividef(1.f, 1.f + __expf(-x));
}
__device__ __forceinline__ float tanhfast(float x) {
    return __fdividef(2.f, 1.f + __expf(-2.f * x)) - 1.f;
}
__device__ __forceinline__ void cpasync16(void* smem, const void* gmem) {
    unsigned s = (unsigned)__cvta_generic_to_shared(smem);
    asm volatile("cp.async.ca.shared.global [%0],[%1],16;" :: "r"(s), "l"(gmem));
}
__device__ __forceinline__ void cpcommit() {
    asm volatile("cp.async.commit_group;");
}

// ---- device scratch (static, allowed) ----
__device__ float g_M[Am*Cch*3];        // folded emb*conv*bn
__device__ float g_bias1[Cch];
__device__ u64   g_wihSplat[2][FK*G4]; // pre-splatted input weights [dir][k][g]
__device__ float g_whhT[2][Hm*G4];     // transposed recurrent weights [dir][k][g]
__device__ float g_fcf[Tm*Hm];
__device__ float g_fcb[Tm*Hm];
__device__ float g_cbias[Tm];
__device__ float g_featT[(size_t)FK*Nt];       // k-major features ~102 MB
__device__ float g_gates[2][(size_t)Nt*G4];    // ~503 MB
__device__ float g_h[2][(size_t)Nt*Hm];        // ~126 MB
__device__ float g_emis[(size_t)Nt*Tm];

// ======================= prep kernels =======================
__global__ void prep_tables(const float* __restrict__ emb,
                            const float* __restrict__ conv_w,
                            const float* __restrict__ conv_b,
                            const float* __restrict__ g1,
                            const float* __restrict__ b1,
                            const float* __restrict__ m1,
                            const float* __restrict__ v1)
{
    int i = blockIdx.x*blockDim.x + threadIdx.x;
    if (i < Am*Cch*3) {
        int k = i % 3;
        int c = (i/3) % Cch;
        int a = i / (3*Cch);
        float s = 0.f;
        for (int e = 0; e < Em; e++)
            s += emb[a*Em + e] * conv_w[(c*Em + e)*3 + k];
        float sc = g1[c] * rsqrtf(v1[c] + 1e-5f);
        g_M[i] = s * sc;
    } else if (i < Am*Cch*3 + Cch) {
        int c = i - Am*Cch*3;
        float sc = g1[c] * rsqrtf(v1[c] + 1e-5f);
        g_bias1[c] = (conv_b[c] - m1[c]) * sc + b1[c];
    }
}

__global__ void prep_pack2(const float* __restrict__ wihf, const float* __restrict__ whhf,
                           const float* __restrict__ wihb, const float* __restrict__ whhb)
{
    int stride = gridDim.x * blockDim.x;
    int t0 = blockIdx.x*blockDim.x + threadIdx.x;
    for (int i = t0; i < FK*G4; i += stride) {
        int k = i / G4, g = i % G4;
        float vf = (k < LIN) ? wihf[g*LIN + k] : 0.f;
        float vb = (k < LIN) ? wihb[g*LIN + k] : 0.f;
        g_wihSplat[0][i] = splat2(vf);
        g_wihSplat[1][i] = splat2(vb);
    }
    for (int i = t0; i < Hm*G4; i += stride) {
        int k = i / G4, g = i % G4;
        g_whhT[0][i] = whhf[g*Hm + k];
        g_whhT[1][i] = whhb[g*Hm + k];
    }
}

__global__ void prep_fc(const float* __restrict__ g2, const float* __restrict__ b2,
                        const float* __restrict__ m2, const float* __restrict__ v2,
                        const float* __restrict__ fcw, const float* __restrict__ fcbias)
{
    int t = threadIdx.x;
    if (t < Hm) {
        float s2a = g2[t]       * rsqrtf(v2[t]       + 1e-5f);
        float s2b = g2[Hm + t]  * rsqrtf(v2[Hm + t]  + 1e-5f);
        for (int tt = 0; tt < Tm; tt++) {
            g_fcf[tt*Hm + t] = fcw[tt*2*Hm + t]      * s2a;
            g_fcb[tt*Hm + t] = fcw[tt*2*Hm + Hm + t] * s2b;
        }
    }
    if (t < Tm) {
        float s = fcbias[t];
        for (int j = 0; j < 2*Hm; j++) {
            float s2 = g2[j] * rsqrtf(v2[j] + 1e-5f);
            s += (b2[j] - m2[j]*s2) * fcw[t*2*Hm + j];
        }
        g_cbias[t] = s;
    }
}

// ======================= featurize (conv+bn+relu+pool), k-major output =======================
__global__ void featurizeT(const int* __restrict__ x)
{
    int n = blockIdx.x*blockDim.x + threadIdx.x;   // token
    int c = blockIdx.y;                            // channel
    if (n >= Nt) return;
    int sym[Wm];
#pragma unroll
    for (int w = 0; w < Wm; w++) sym[w] = x[n*Wm + w];
    float y[Wm];
    float bb = g_bias1[c];
#pragma unroll
    for (int w = 0; w < Wm; w++) {
        float v = bb;
#pragma unroll
        for (int k = 0; k < 3; k++) {
            int p = w + k - 1;
            if (p >= 0 && p < Wm)
                v += g_M[sym[p]*(Cch*3) + c*3 + k];
        }
        y[w] = fmaxf(v, 0.f);
    }
#pragma unroll
    for (int w = 0; w < Wm; w++) {
        float p = y[w];
        if (w > 0)      p = fmaxf(p, y[w-1]);
        if (w < Wm-1)   p = fmaxf(p, y[w+1]);
        g_featT[(size_t)(c*Wm + w)*Nt + n] = p;    // k-major
    }
    if (c == 0) {
#pragma unroll
        for (int k = LIN; k < FK; k++)
            g_featT[(size_t)k*Nt + n] = 0.f;
    }
}

// ======================= input GEMM v5 (f32x2, 128x128, cp.async double-buffered) =======================
// block tile 128(M) x 128(N), 256 threads, per-thread 8(M as 4 f32x2 pairs) x 8(N).
// Accumulator i holds gate column n0 + i*16 + tn (matches the [k][g] smem B layout).
__global__ __launch_bounds__(256, 2) void gemm_gates5(const float* __restrict__ bias_f,
                                                      const float* __restrict__ bias_b)
{
    int dir = blockIdx.x >> 2;
    int n0  = (blockIdx.x & 3) * 128;
    int m0  = blockIdx.y * 128;
    const float* __restrict__ A  = g_featT;          // [FK][Nt]
    const u64*   __restrict__ Bw = g_wihSplat[dir];  // [FK][G4]
    float* __restrict__ Co = g_gates[dir];
    const float* __restrict__ bias = dir ? bias_b : bias_f;

    __shared__ __align__(16) float Asf[2][16][128];  // [buf][k][row]
    __shared__ __align__(16) u64   Bsp[2][16][128];  // [buf][k][g] pre-splatted

    int t  = threadIdx.x;
    int tm = t >> 4;          // 0..15 -> 8 M rows (4 pairs)
    int tn = t & 15;          // 0..15 -> N lane

    // cp.async thread mapping
    int akk  = t >> 5;         // 0..7 (k within chunk, +8 second round)
    int arow = (t & 31) * 4;   // 4 rows per 16B

    u64 acc2[4][8];
#pragma unroll
    for (int q = 0; q < 4; q++)
#pragma unroll
        for (int i = 0; i < 8; i++) acc2[q][i] = 0ULL;

    // --- async load of one chunk into buffer `buf` ---
    auto load_chunk = [&](int c, int buf) {
        int k0 = c*16;
#pragma unroll
        for (int r = 0; r < 2; r++) {
            int kk = akk + r*8;
            cpasync16(&Asf[buf][kk][arow],
                      A + (size_t)(k0 + kk)*Nt + m0 + arow);
        }
#pragma unroll
        for (int r = 0; r < 4; r++) {
            int s   = r*256 + t;          // 16B chunk index
            int kkb = s >> 6;             // 64 chunks of 16B per k row (128 u64)
            int off = (s & 63) * 2;       // u64 offset
            cpasync16(&Bsp[buf][kkb][off],
                      Bw + (size_t)(k0 + kkb)*G4 + n0 + off);
        }
        cpcommit();
    };

    load_chunk(0, 0);

    int cur = 0;
    for (int c = 0; c < NCH; c++) {
        if (c + 1 < NCH) {
            load_chunk(c + 1, cur ^ 1);
            asm volatile("cp.async.wait_group 1;");
        } else {
            asm volatile("cp.async.wait_group 0;");
        }
        __syncthreads();
#pragma unroll
        for (int kk = 0; kk < 16; kk++) {
            const u64* ap64 = (const u64*)&Asf[cur][kk][tm*8];
            u64 am0 = ap64[0], am1 = ap64[1], am2 = ap64[2], am3 = ap64[3];
            u64 bs[8];
#pragma unroll
            for (int i = 0; i < 8; i++) bs[i] = Bsp[cur][kk][i*16 + tn];
#pragma unroll
            for (int i = 0; i < 8; i++) {
                acc2[0][i] = fma2(am0, bs[i], acc2[0][i]);
                acc2[1][i] = fma2(am1, bs[i], acc2[1][i]);
                acc2[2][i] = fma2(am2, bs[i], acc2[2][i]);
                acc2[3][i] = fma2(am3, bs[i], acc2[3][i]);
            }
        }
        __syncthreads();
        cur ^= 1;
    }

    // epilogue: accumulator i -> gate column n0 + i*16 + tn
    float bb[8];
#pragma unroll
    for (int i = 0; i < 8; i++) bb[i] = bias[n0 + i*16 + tn];
#pragma unroll
    for (int q = 0; q < 4; q++) {
        size_t r = (size_t)(m0 + tm*8 + 2*q);
#pragma unroll
        for (int i = 0; i < 8; i++) {
            float lo, hi;
            unpack2(acc2[q][i], lo, hi);
            int col = n0 + i*16 + tn;
            Co[r*G4 + col]     = lo + bb[i];
            Co[(r+1)*G4 + col] = hi + bb[i];
        }
    }
}

// ======================= LSTM recurrence (both dirs fused, f32x2) =======================
__global__ __launch_bounds__(256, 2) void lstm_fused()
{
    int dir = blockIdx.x >> 7;
    int blk = blockIdx.x & 127;
    const float* __restrict__ gates = g_gates[dir];
    const float* __restrict__ whhT  = g_whhT[dir];
    float* __restrict__ hout        = g_h[dir];

    __shared__ __align__(16) float hs[2][Hm][36];

    int t = threadIdx.x;
    int j = t & 127;
    int half = t >> 7;
    int r0 = blk * 32 + half * 16;

    for (int i = t; i < 2*Hm*36; i += 256) ((float*)hs)[i] = 0.f;

    float cst[16];
#pragma unroll
    for (int r = 0; r < 16; r++) cst[r] = 0.f;
    __syncthreads();

    int cur = 0;
    const float* wp = whhT + j;

    for (int li = 0; li < Lm; li++) {
        int l = dir ? (Lm-1-li) : li;

        u64 acc2[4][8];
#pragma unroll
        for (int g = 0; g < 4; g++)
#pragma unroll
            for (int q = 0; q < 8; q++) {
                size_t base = ((size_t)(r0 + 2*q)*Lm + l)*G4 + g*128 + j;
                float lo = gates[base];
                float hi = gates[base + (size_t)Lm*G4];
                acc2[g][q] = pack2(lo, hi);
            }

#pragma unroll 4
        for (int k = 0; k < Hm; k++) {
            float w0 = wp[k*G4 + 0];
            float w1 = wp[k*G4 + 128];
            float w2 = wp[k*G4 + 256];
            float w3 = wp[k*G4 + 384];
            u64 w0p = splat2(w0), w1p = splat2(w1);
            u64 w2p = splat2(w2), w3p = splat2(w3);
            const ulonglong2* hp = (const ulonglong2*)&hs[cur][k][half*16];
#pragma unroll
            for (int qq = 0; qq < 4; qq++) {
                ulonglong2 hv2 = hp[qq];
                acc2[0][2*qq]   = fma2(w0p, hv2.x, acc2[0][2*qq]);
                acc2[1][2*qq]   = fma2(w1p, hv2.x, acc2[1][2*qq]);
                acc2[2][2*qq]   = fma2(w2p, hv2.x, acc2[2][2*qq]);
                acc2[3][2*qq]   = fma2(w3p, hv2.x, acc2[3][2*qq]);
                acc2[0][2*qq+1] = fma2(w0p, hv2.y, acc2[0][2*qq+1]);
                acc2[1][2*qq+1] = fma2(w1p, hv2.y, acc2[1][2*qq+1]);
                acc2[2][2*qq+1] = fma2(w2p, hv2.y, acc2[2][2*qq+1]);
                acc2[3][2*qq+1] = fma2(w3p, hv2.y, acc2[3][2*qq+1]);
            }
        }

#pragma unroll
        for (int q = 0; q < 8; q++) {
            float zi0,zi1,zf0,zf1,zg0,zg1,zo0,zo1;
            unpack2(acc2[0][q], zi0, zi1);
            unpack2(acc2[1][q], zf0, zf1);
            unpack2(acc2[2][q], zg0, zg1);
            unpack2(acc2[3][q], zo0, zo1);
            {
                float ig = sigf(zi0), fg = sigf(zf0);
                float gg = tanhfast(zg0), og = sigf(zo0);
                float cn = fg*cst[2*q] + ig*gg;
                cst[2*q] = cn;
                float hn = og * tanhfast(cn);
                hs[cur^1][j][half*16 + 2*q] = hn;
                hout[((size_t)(r0 + 2*q)*Lm + l)*Hm + j] = hn;
            }
            {
                float ig = sigf(zi1), fg = sigf(zf1);
                float gg = tanhfast(zg1), og = sigf(zo1);
                float cn = fg*cst[2*q+1] + ig*gg;
                cst[2*q+1] = cn;
                float hn = og * tanhfast(cn);
                hs[cur^1][j][half*16 + 2*q + 1] = hn;
                hout[((size_t)(r0 + 2*q + 1)*Lm + l)*Hm + j] = hn;
            }
        }
        cur ^= 1;
        __syncthreads();
    }
}

// ======================= emission (BN2+FC folded) =======================
__global__ void emission_kernel()
{
    int gt = blockIdx.x*blockDim.x + threadIdx.x;
    int warp = gt >> 5;
    int lane = threadIdx.x & 31;
    if (warp >= Nt) return;
    float4 hf4 = *(const float4*)&g_h[0][(size_t)warp*Hm + lane*4];
    float4 hb4 = *(const float4*)&g_h[1][(size_t)warp*Hm + lane*4];
#pragma unroll
    for (int tt = 0; tt < Tm; tt++) {
        float4 f4 = *(const float4*)&g_fcf[tt*Hm + lane*4];
        float4 b4 = *(const float4*)&g_fcb[tt*Hm + lane*4];
        float s = hf4.x*f4.x + hf4.y*f4.y + hf4.z*f4.z + hf4.w*f4.w
                + hb4.x*b4.x + hb4.y*b4.y + hb4.z*b4.z + hb4.w*b4.w;
#pragma unroll
        for (int o = 16; o; o >>= 1) s += __shfl_xor_sync(0xffffffffu, s, o);
        if (lane == 0) g_emis[(size_t)warp*Tm + tt] = s + g_cbias[tt];
    }
}

// ======================= Viterbi =======================
__global__ void viterbi_kernel(const int* __restrict__ x,
                               const float* __restrict__ trans,
                               const float* __restrict__ start_t,
                               const float* __restrict__ end_t,
                               float* __restrict__ out)
{
    int b = blockIdx.x*blockDim.x + threadIdx.x;
    if (b >= Bsz) return;
    float tr[9];
#pragma unroll
    for (int i = 0; i < 9; i++) tr[i] = trans[i];
    const float* em = g_emis + (size_t)b*Lm*Tm;
    float sc[3];
#pragma unroll
    for (int t = 0; t < 3; t++) sc[t] = start_t[t] + em[t];

    unsigned char hist[Lm-1][3];
    for (int l = 1; l < Lm; l++) {
        bool m = x[(b*Lm + l)*Wm + 2] > 0;
        float ns[3];
#pragma unroll
        for (int t = 0; t < 3; t++) {
            float best = sc[0] + tr[0*3 + t];
            int bp = 0;
#pragma unroll
            for (int p = 1; p < 3; p++) {
                float v = sc[p] + tr[p*3 + t];
                if (v > best) { best = v; bp = p; }
            }
            hist[l-1][t] = (unsigned char)bp;
            ns[t] = best + em[l*Tm + t];
        }
        if (m) { sc[0]=ns[0]; sc[1]=ns[1]; sc[2]=ns[2]; }
    }
#pragma unroll
    for (int t = 0; t < 3; t++) sc[t] += end_t[t];
    float best = sc[0]; int last = 0;
    if (sc[1] > best) { best = sc[1]; last = 1; }
    if (sc[2] > best) { best = sc[2]; last = 2; }
    out[b] = best;

    float* tagout = out + Bsz;
    int tag = last;
    tagout[(size_t)b*Lm + (Lm-1)] = (float)tag;
    for (int i = Lm-2; i >= 0; i--) {
        int prev = hist[i][tag];
        bool m = x[(b*Lm + i + 1)*Wm + 2] > 0;
        if (m) tag = prev;
        tagout[(size_t)b*Lm + i] = (float)tag;
    }
}

// ======================= launch =======================
extern "C" void kernel_launch(void* const* d_in, const int* in_sizes, int n_in,
                              void* d_out, int out_size)
{
    (void)in_sizes; (void)n_in; (void)out_size;
    const int*   x      = (const int*)  d_in[0];
    const float* emb    = (const float*)d_in[1];
    const float* conv_w = (const float*)d_in[2];
    const float* conv_b = (const float*)d_in[3];
    const float* bn1_g  = (const float*)d_in[4];
    const float* bn1_b  = (const float*)d_in[5];
    const float* bn1_m  = (const float*)d_in[6];
    const float* bn1_v  = (const float*)d_in[7];
    const float* w_ih_f = (const float*)d_in[8];
    const float* w_hh_f = (const float*)d_in[9];
    const float* b_f    = (const float*)d_in[10];
    const float* w_ih_b = (const float*)d_in[11];
    const float* w_hh_b = (const float*)d_in[12];
    const float* b_b    = (const float*)d_in[13];
    const float* bn2_g  = (const float*)d_in[14];
    const float* bn2_b  = (const float*)d_in[15];
    const float* bn2_m  = (const float*)d_in[16];
    const float* bn2_v  = (const float*)d_in[17];
    const float* fc_w   = (const float*)d_in[18];
    const float* fc_b   = (const float*)d_in[19];
    const float* trans  = (const float*)d_in[20];
    const float* start_t= (const float*)d_in[21];
    const float* end_t  = (const float*)d_in[22];
    float* out = (float*)d_out;

    prep_tables<<<(Am*Cch*3 + Cch + 255)/256, 256>>>(emb, conv_w, conv_b,
                                                     bn1_g, bn1_b, bn1_m, bn1_v);
    prep_pack2<<<512, 256>>>(w_ih_f, w_hh_f, w_ih_b, w_hh_b);
    prep_fc<<<1, 256>>>(bn2_g, bn2_b, bn2_m, bn2_v, fc_w, fc_b);

    dim3 fg(Nt/256, Cch);
    featurizeT<<<fg, 256>>>(x);

    dim3 gg(8, Nt/128);
    gemm_gates5<<<gg, 256>>>(b_f, b_b);

    lstm_fused<<<256, 256>>>();

    emission_kernel<<<(Nt + 3)/4, 128>>>();

    viterbi_kernel<<<(Bsz + 127)/128, 128>>>(x, trans, start_t, end_t, out);
}

// round 7
// speedup vs baseline: 1.2249x; 1.1362x over previous
#include <cuda_runtime.h>
#include <math.h>
#include <stdint.h>

// ---- problem constants ----
#define Bsz 4096
#define Lm  30
#define Wm  5
#define Am  30
#define Em  128
#define Cch 40
#define Hm  128
#define Tm  3
#define LIN 200
#define FK  208          // padded K for GEMM
#define Nt  (Bsz*Lm)     // 122880 tokens
#define G4  512          // 4*H gates
#define KC  8            // k-chunk
#define NCH (FK/KC)      // 26 chunks

typedef unsigned long long u64;

// ---- packed f32x2 helpers (FFMA2 path, sm_103a) ----
__device__ __forceinline__ u64 pack2(float lo, float hi) {
    u64 r; asm("mov.b64 %0,{%1,%2};" : "=l"(r) : "f"(lo), "f"(hi)); return r;
}
__device__ __forceinline__ u64 splat2(float v) { return pack2(v, v); }
__device__ __forceinline__ u64 fma2(u64 a, u64 b, u64 c) {
    u64 d; asm("fma.rn.f32x2 %0,%1,%2,%3;" : "=l"(d) : "l"(a), "l"(b), "l"(c)); return d;
}
__device__ __forceinline__ void unpack2(u64 v, float& lo, float& hi) {
    asm("mov.b64 {%0,%1},%2;" : "=f"(lo), "=f"(hi) : "l"(v));
}
__device__ __forceinline__ float sigf(float x) {
    return __fdividef(1.f, 1.f + __expf(-x));
}
__device__ __forceinline__ float tanhfast(float x) {
    return __fdividef(2.f, 1.f + __expf(-2.f * x)) - 1.f;
}
__device__ __forceinline__ void cpasync16(void* smem, const void* gmem) {
    unsigned s = (unsigned)__cvta_generic_to_shared(smem);
    asm volatile("cp.async.ca.shared.global [%0],[%1],16;" :: "r"(s), "l"(gmem));
}
__device__ __forceinline__ void cpcommit() {
    asm volatile("cp.async.commit_group;");
}
__device__ __forceinline__ float to_tf32(float x) {
    uint32_t u; asm("cvt.rna.tf32.f32 %0,%1;" : "=r"(u) : "f"(x));
    return __uint_as_float(u);
}
__device__ __forceinline__ void mma_tf32(float* d, const uint32_t* a,
                                         uint32_t b0, uint32_t b1) {
    asm("mma.sync.aligned.m16n8k8.row.col.f32.tf32.tf32.f32 "
        "{%0,%1,%2,%3},{%4,%5,%6,%7},{%8,%9},{%0,%1,%2,%3};"
        : "+f"(d[0]), "+f"(d[1]), "+f"(d[2]), "+f"(d[3])
        : "r"(a[0]), "r"(a[1]), "r"(a[2]), "r"(a[3]), "r"(b0), "r"(b1));
}

// ---- device scratch (static, allowed) ----
__device__ float g_M[Am*Cch*3];
__device__ float g_bias1[Cch];
__device__ float g_wihT[2][2*FK*G4];   // [dir][hi|lo plane][k][g]
__device__ float g_whhT[2][Hm*G4];     // fp32 recurrent weights [dir][k][g]
__device__ float g_fcf[Tm*Hm];
__device__ float g_fcb[Tm*Hm];
__device__ float g_cbias[Tm];
__device__ float g_featT[(size_t)2*FK*Nt];     // hi plane [0..FK), lo plane [FK..2FK)
__device__ float g_gates[2][(size_t)Nt*G4];
__device__ float g_h[2][(size_t)Nt*Hm];
__device__ float g_emis[(size_t)Nt*Tm];

// ======================= prep kernels =======================
__global__ void prep_tables(const float* __restrict__ emb,
                            const float* __restrict__ conv_w,
                            const float* __restrict__ conv_b,
                            const float* __restrict__ g1,
                            const float* __restrict__ b1,
                            const float* __restrict__ m1,
                            const float* __restrict__ v1)
{
    int i = blockIdx.x*blockDim.x + threadIdx.x;
    if (i < Am*Cch*3) {
        int k = i % 3;
        int c = (i/3) % Cch;
        int a = i / (3*Cch);
        float s = 0.f;
        for (int e = 0; e < Em; e++)
            s += emb[a*Em + e] * conv_w[(c*Em + e)*3 + k];
        float sc = g1[c] * rsqrtf(v1[c] + 1e-5f);
        g_M[i] = s * sc;
    } else if (i < Am*Cch*3 + Cch) {
        int c = i - Am*Cch*3;
        float sc = g1[c] * rsqrtf(v1[c] + 1e-5f);
        g_bias1[c] = (conv_b[c] - m1[c]) * sc + b1[c];
    }
}

__global__ void prep_pack4(const float* __restrict__ wihf, const float* __restrict__ whhf,
                           const float* __restrict__ wihb, const float* __restrict__ whhb)
{
    int stride = gridDim.x * blockDim.x;
    int t0 = blockIdx.x*blockDim.x + threadIdx.x;
    for (int i = t0; i < FK*G4; i += stride) {
        int k = i / G4, g = i % G4;
        float vf = (k < LIN) ? wihf[g*LIN + k] : 0.f;
        float vb = (k < LIN) ? wihb[g*LIN + k] : 0.f;
        float hf = to_tf32(vf), hb = to_tf32(vb);
        g_wihT[0][i]           = hf;
        g_wihT[0][FK*G4 + i]   = to_tf32(vf - hf);
        g_wihT[1][i]           = hb;
        g_wihT[1][FK*G4 + i]   = to_tf32(vb - hb);
    }
    for (int i = t0; i < Hm*G4; i += stride) {
        int k = i / G4, g = i % G4;
        g_whhT[0][i] = whhf[g*Hm + k];
        g_whhT[1][i] = whhb[g*Hm + k];
    }
}

__global__ void prep_fc(const float* __restrict__ g2, const float* __restrict__ b2,
                        const float* __restrict__ m2, const float* __restrict__ v2,
                        const float* __restrict__ fcw, const float* __restrict__ fcbias)
{
    int t = threadIdx.x;
    if (t < Hm) {
        float s2a = g2[t]       * rsqrtf(v2[t]       + 1e-5f);
        float s2b = g2[Hm + t]  * rsqrtf(v2[Hm + t]  + 1e-5f);
        for (int tt = 0; tt < Tm; tt++) {
            g_fcf[tt*Hm + t] = fcw[tt*2*Hm + t]      * s2a;
            g_fcb[tt*Hm + t] = fcw[tt*2*Hm + Hm + t] * s2b;
        }
    }
    if (t < Tm) {
        float s = fcbias[t];
        for (int j = 0; j < 2*Hm; j++) {
            float s2 = g2[j] * rsqrtf(v2[j] + 1e-5f);
            s += (b2[j] - m2[j]*s2) * fcw[t*2*Hm + j];
        }
        g_cbias[t] = s;
    }
}

// ======================= featurize, k-major hi/lo planes =======================
__global__ void featurizeT(const int* __restrict__ x)
{
    int n = blockIdx.x*blockDim.x + threadIdx.x;
    int c = blockIdx.y;
    if (n >= Nt) return;
    int sym[Wm];
#pragma unroll
    for (int w = 0; w < Wm; w++) sym[w] = x[n*Wm + w];
    float y[Wm];
    float bb = g_bias1[c];
#pragma unroll
    for (int w = 0; w < Wm; w++) {
        float v = bb;
#pragma unroll
        for (int k = 0; k < 3; k++) {
            int p = w + k - 1;
            if (p >= 0 && p < Wm)
                v += g_M[sym[p]*(Cch*3) + c*3 + k];
        }
        y[w] = fmaxf(v, 0.f);
    }
#pragma unroll
    for (int w = 0; w < Wm; w++) {
        float p = y[w];
        if (w > 0)      p = fmaxf(p, y[w-1]);
        if (w < Wm-1)   p = fmaxf(p, y[w+1]);
        float hi = to_tf32(p);
        g_featT[(size_t)(c*Wm + w)*Nt + n]        = hi;
        g_featT[(size_t)(FK + c*Wm + w)*Nt + n]   = to_tf32(p - hi);
    }
    if (c == 0) {
#pragma unroll
        for (int k = LIN; k < FK; k++) {
            g_featT[(size_t)k*Nt + n]        = 0.f;
            g_featT[(size_t)(FK + k)*Nt + n] = 0.f;
        }
    }
}

// ======================= input GEMM v7: split-tf32 3-pass mma =======================
// 128x128 block, 8 warps (wm=w&3 -> 32 M rows, wn=w>>2 -> 64 N cols).
// K-chunk 8; 4 smem planes (A_hi, A_lo, B_hi, B_lo) double-buffered = 32KB.
__global__ __launch_bounds__(256, 2) void gemm_tf32s(const float* __restrict__ bias_f,
                                                     const float* __restrict__ bias_b)
{
    int dir = blockIdx.x >> 2;
    int n0  = (blockIdx.x & 3) * 128;
    int m0  = blockIdx.y * 128;
    const float* __restrict__ Ah = g_featT;                    // [FK][Nt]
    const float* __restrict__ Al = g_featT + (size_t)FK*Nt;
    const float* __restrict__ Bh = g_wihT[dir];                // [FK][G4]
    const float* __restrict__ Bl = g_wihT[dir] + FK*G4;
    float* __restrict__ Co = g_gates[dir];
    const float* __restrict__ bias = dir ? bias_b : bias_f;

    __shared__ __align__(16) float Ash[2][KC][128];
    __shared__ __align__(16) float Asl[2][KC][128];
    __shared__ __align__(16) float Bsh[2][KC][128];
    __shared__ __align__(16) float Bsl[2][KC][128];

    int t    = threadIdx.x;
    int lane = t & 31;
    int w    = t >> 5;
    int wm   = w & 3;
    int wn   = w >> 2;
    int gi   = lane >> 2;    // 0..7
    int li   = lane & 3;     // 0..3

    float acc[2][8][4];
#pragma unroll
    for (int mt = 0; mt < 2; mt++)
#pragma unroll
        for (int nt = 0; nt < 8; nt++)
#pragma unroll
            for (int q = 0; q < 4; q++) acc[mt][nt][q] = 0.f;

    int kk = t >> 5;             // 0..7
    int c4 = (t & 31) * 4;
    int sw = c4 ^ ((kk & 3) << 3);

    auto load_chunk = [&](int c, int buf) {
        size_t ka = (size_t)(c*KC + kk);
        cpasync16(&Ash[buf][kk][sw], Ah + ka*Nt + m0 + c4);
        cpasync16(&Asl[buf][kk][sw], Al + ka*Nt + m0 + c4);
        cpasync16(&Bsh[buf][kk][sw], Bh + ka*G4 + n0 + c4);
        cpasync16(&Bsl[buf][kk][sw], Bl + ka*G4 + n0 + c4);
        cpcommit();
    };

    load_chunk(0, 0);

    int cur = 0;
    for (int c = 0; c < NCH; c++) {
        if (c + 1 < NCH) {
            load_chunk(c + 1, cur ^ 1);
            asm volatile("cp.async.wait_group 1;");
        } else {
            asm volatile("cp.async.wait_group 0;");
        }
        __syncthreads();

        int kA = li, kB = li + 4;
        int sA = (kA & 3) << 3;
        int sB = (kB & 3) << 3;
        uint32_t ah[2][4], al[2][4];
#pragma unroll
        for (int mt = 0; mt < 2; mt++) {
            int r0 = wm*32 + mt*16 + gi;
            ah[mt][0] = __float_as_uint(Ash[cur][kA][ r0      ^ sA]);
            ah[mt][1] = __float_as_uint(Ash[cur][kA][(r0 + 8) ^ sA]);
            ah[mt][2] = __float_as_uint(Ash[cur][kB][ r0      ^ sB]);
            ah[mt][3] = __float_as_uint(Ash[cur][kB][(r0 + 8) ^ sB]);
            al[mt][0] = __float_as_uint(Asl[cur][kA][ r0      ^ sA]);
            al[mt][1] = __float_as_uint(Asl[cur][kA][(r0 + 8) ^ sA]);
            al[mt][2] = __float_as_uint(Asl[cur][kB][ r0      ^ sB]);
            al[mt][3] = __float_as_uint(Asl[cur][kB][(r0 + 8) ^ sB]);
        }
#pragma unroll
        for (int nt = 0; nt < 8; nt++) {
            int col = wn*64 + nt*8 + gi;
            uint32_t bh0 = __float_as_uint(Bsh[cur][kA][col ^ sA]);
            uint32_t bh1 = __float_as_uint(Bsh[cur][kB][col ^ sB]);
            uint32_t bl0 = __float_as_uint(Bsl[cur][kA][col ^ sA]);
            uint32_t bl1 = __float_as_uint(Bsl[cur][kB][col ^ sB]);
#pragma unroll
            for (int mt = 0; mt < 2; mt++) {
                mma_tf32(acc[mt][nt], al[mt], bh0, bh1);   // lo*hi
                mma_tf32(acc[mt][nt], ah[mt], bl0, bl1);   // hi*lo
                mma_tf32(acc[mt][nt], ah[mt], bh0, bh1);   // hi*hi
            }
        }
        __syncthreads();
        cur ^= 1;
    }

#pragma unroll
    for (int mt = 0; mt < 2; mt++) {
        size_t r0 = (size_t)(m0 + wm*32 + mt*16 + gi);
#pragma unroll
        for (int nt = 0; nt < 8; nt++) {
            int col = n0 + wn*64 + nt*8 + 2*li;
            float b0 = bias[col], b1 = bias[col + 1];
            float2 v;
            v.x = acc[mt][nt][0] + b0; v.y = acc[mt][nt][1] + b1;
            *(float2*)(Co + r0*G4 + col) = v;
            v.x = acc[mt][nt][2] + b0; v.y = acc[mt][nt][3] + b1;
            *(float2*)(Co + (r0 + 8)*G4 + col) = v;
        }
    }
}

// ======================= LSTM recurrence (both dirs fused, f32x2) =======================
__global__ __launch_bounds__(256, 2) void lstm_fused()
{
    int dir = blockIdx.x >> 7;
    int blk = blockIdx.x & 127;
    const float* __restrict__ gates = g_gates[dir];
    const float* __restrict__ whhT  = g_whhT[dir];
    float* __restrict__ hout        = g_h[dir];

    __shared__ __align__(16) float hs[2][Hm][36];

    int t = threadIdx.x;
    int j = t & 127;
    int half = t >> 7;
    int r0 = blk * 32 + half * 16;

    for (int i = t; i < 2*Hm*36; i += 256) ((float*)hs)[i] = 0.f;

    float cst[16];
#pragma unroll
    for (int r = 0; r < 16; r++) cst[r] = 0.f;
    __syncthreads();

    int cur = 0;
    const float* wp = whhT + j;

    for (int li = 0; li < Lm; li++) {
        int l = dir ? (Lm-1-li) : li;

        u64 acc2[4][8];
#pragma unroll
        for (int g = 0; g < 4; g++)
#pragma unroll
            for (int q = 0; q < 8; q++) {
                size_t base = ((size_t)(r0 + 2*q)*Lm + l)*G4 + g*128 + j;
                float lo = gates[base];
                float hi = gates[base + (size_t)Lm*G4];
                acc2[g][q] = pack2(lo, hi);
            }

#pragma unroll 4
        for (int k = 0; k < Hm; k++) {
            float w0 = wp[k*G4 + 0];
            float w1 = wp[k*G4 + 128];
            float w2 = wp[k*G4 + 256];
            float w3 = wp[k*G4 + 384];
            u64 w0p = splat2(w0), w1p = splat2(w1);
            u64 w2p = splat2(w2), w3p = splat2(w3);
            const ulonglong2* hp = (const ulonglong2*)&hs[cur][k][half*16];
#pragma unroll
            for (int qq = 0; qq < 4; qq++) {
                ulonglong2 hv2 = hp[qq];
                acc2[0][2*qq]   = fma2(w0p, hv2.x, acc2[0][2*qq]);
                acc2[1][2*qq]   = fma2(w1p, hv2.x, acc2[1][2*qq]);
                acc2[2][2*qq]   = fma2(w2p, hv2.x, acc2[2][2*qq]);
                acc2[3][2*qq]   = fma2(w3p, hv2.x, acc2[3][2*qq]);
                acc2[0][2*qq+1] = fma2(w0p, hv2.y, acc2[0][2*qq+1]);
                acc2[1][2*qq+1] = fma2(w1p, hv2.y, acc2[1][2*qq+1]);
                acc2[2][2*qq+1] = fma2(w2p, hv2.y, acc2[2][2*qq+1]);
                acc2[3][2*qq+1] = fma2(w3p, hv2.y, acc2[3][2*qq+1]);
            }
        }

#pragma unroll
        for (int q = 0; q < 8; q++) {
            float zi0,zi1,zf0,zf1,zg0,zg1,zo0,zo1;
            unpack2(acc2[0][q], zi0, zi1);
            unpack2(acc2[1][q], zf0, zf1);
            unpack2(acc2[2][q], zg0, zg1);
            unpack2(acc2[3][q], zo0, zo1);
            {
                float ig = sigf(zi0), fg = sigf(zf0);
                float gg = tanhfast(zg0), og = sigf(zo0);
                float cn = fg*cst[2*q] + ig*gg;
                cst[2*q] = cn;
                float hn = og * tanhfast(cn);
                hs[cur^1][j][half*16 + 2*q] = hn;
                hout[((size_t)(r0 + 2*q)*Lm + l)*Hm + j] = hn;
            }
            {
                float ig = sigf(zi1), fg = sigf(zf1);
                float gg = tanhfast(zg1), og = sigf(zo1);
                float cn = fg*cst[2*q+1] + ig*gg;
                cst[2*q+1] = cn;
                float hn = og * tanhfast(cn);
                hs[cur^1][j][half*16 + 2*q + 1] = hn;
                hout[((size_t)(r0 + 2*q + 1)*Lm + l)*Hm + j] = hn;
            }
        }
        cur ^= 1;
        __syncthreads();
    }
}

// ======================= emission (BN2+FC folded) =======================
__global__ void emission_kernel()
{
    int gt = blockIdx.x*blockDim.x + threadIdx.x;
    int warp = gt >> 5;
    int lane = threadIdx.x & 31;
    if (warp >= Nt) return;
    float4 hf4 = *(const float4*)&g_h[0][(size_t)warp*Hm + lane*4];
    float4 hb4 = *(const float4*)&g_h[1][(size_t)warp*Hm + lane*4];
#pragma unroll
    for (int tt = 0; tt < Tm; tt++) {
        float4 f4 = *(const float4*)&g_fcf[tt*Hm + lane*4];
        float4 b4 = *(const float4*)&g_fcb[tt*Hm + lane*4];
        float s = hf4.x*f4.x + hf4.y*f4.y + hf4.z*f4.z + hf4.w*f4.w
                + hb4.x*b4.x + hb4.y*b4.y + hb4.z*b4.z + hb4.w*b4.w;
#pragma unroll
        for (int o = 16; o; o >>= 1) s += __shfl_xor_sync(0xffffffffu, s, o);
        if (lane == 0) g_emis[(size_t)warp*Tm + tt] = s + g_cbias[tt];
    }
}

// ======================= Viterbi =======================
__global__ void viterbi_kernel(const int* __restrict__ x,
                               const float* __restrict__ trans,
                               const float* __restrict__ start_t,
                               const float* __restrict__ end_t,
                               float* __restrict__ out)
{
    int b = blockIdx.x*blockDim.x + threadIdx.x;
    if (b >= Bsz) return;
    float tr[9];
#pragma unroll
    for (int i = 0; i < 9; i++) tr[i] = trans[i];
    const float* em = g_emis + (size_t)b*Lm*Tm;
    float sc[3];
#pragma unroll
    for (int t = 0; t < 3; t++) sc[t] = start_t[t] + em[t];

    unsigned char hist[Lm-1][3];
    for (int l = 1; l < Lm; l++) {
        bool m = x[(b*Lm + l)*Wm + 2] > 0;
        float ns[3];
#pragma unroll
        for (int t = 0; t < 3; t++) {
            float best = sc[0] + tr[0*3 + t];
            int bp = 0;
#pragma unroll
            for (int p = 1; p < 3; p++) {
                float v = sc[p] + tr[p*3 + t];
                if (v > best) { best = v; bp = p; }
            }
            hist[l-1][t] = (unsigned char)bp;
            ns[t] = best + em[l*Tm + t];
        }
        if (m) { sc[0]=ns[0]; sc[1]=ns[1]; sc[2]=ns[2]; }
    }
#pragma unroll
    for (int t = 0; t < 3; t++) sc[t] += end_t[t];
    float best = sc[0]; int last = 0;
    if (sc[1] > best) { best = sc[1]; last = 1; }
    if (sc[2] > best) { best = sc[2]; last = 2; }
    out[b] = best;

    float* tagout = out + Bsz;
    int tag = last;
    tagout[(size_t)b*Lm + (Lm-1)] = (float)tag;
    for (int i = Lm-2; i >= 0; i--) {
        int prev = hist[i][tag];
        bool m = x[(b*Lm + i + 1)*Wm + 2] > 0;
        if (m) tag = prev;
        tagout[(size_t)b*Lm + i] = (float)tag;
    }
}

// ======================= launch =======================
extern "C" void kernel_launch(void* const* d_in, const int* in_sizes, int n_in,
                              void* d_out, int out_size)
{
    (void)in_sizes; (void)n_in; (void)out_size;
    const int*   x      = (const int*)  d_in[0];
    const float* emb    = (const float*)d_in[1];
    const float* conv_w = (const float*)d_in[2];
    const float* conv_b = (const float*)d_in[3];
    const float* bn1_g  = (const float*)d_in[4];
    const float* bn1_b  = (const float*)d_in[5];
    const float* bn1_m  = (const float*)d_in[6];
    const float* bn1_v  = (const float*)d_in[7];
    const float* w_ih_f = (const float*)d_in[8];
    const float* w_hh_f = (const float*)d_in[9];
    const float* b_f    = (const float*)d_in[10];
    const float* w_ih_b = (const float*)d_in[11];
    const float* w_hh_b = (const float*)d_in[12];
    const float* b_b    = (const float*)d_in[13];
    const float* bn2_g  = (const float*)d_in[14];
    const float* bn2_b  = (const float*)d_in[15];
    const float* bn2_m  = (const float*)d_in[16];
    const float* bn2_v  = (const float*)d_in[17];
    const float* fc_w   = (const float*)d_in[18];
    const float* fc_b   = (const float*)d_in[19];
    const float* trans  = (const float*)d_in[20];
    const float* start_t= (const float*)d_in[21];
    const float* end_t  = (const float*)d_in[22];
    float* out = (float*)d_out;

    prep_tables<<<(Am*Cch*3 + Cch + 255)/256, 256>>>(emb, conv_w, conv_b,
                                                     bn1_g, bn1_b, bn1_m, bn1_v);
    prep_pack4<<<512, 256>>>(w_ih_f, w_hh_f, w_ih_b, w_hh_b);
    prep_fc<<<1, 256>>>(bn2_g, bn2_b, bn2_m, bn2_v, fc_w, fc_b);

    dim3 fg(Nt/256, Cch);
    featurizeT<<<fg, 256>>>(x);

    dim3 gg(8, Nt/128);
    gemm_tf32s<<<gg, 256>>>(b_f, b_b);

    lstm_fused<<<256, 256>>>();

    emission_kernel<<<(Nt + 3)/4, 128>>>();

    viterbi_kernel<<<(Bsz + 127)/128, 128>>>(x, trans, start_t, end_t, out);
}